// round 12
// baseline (speedup 1.0000x reference)
#include <cuda_runtime.h>
#include <cstdint>

#define B    32
#define D    1024   // CTX_DIM
#define C    2048   // CTX_SIZE
#define H    1024   // HID
#define HC   32     // h-chunks in kernel A
#define HCH  (H/HC) // 32 h per chunk
#define CCH  16     // context columns per chunk
#define GCH  32     // chunks per CTA
#define NCHB (C/(CCH*GCH))  // 4 CTA-groups per batch -> grid 128
#define ROWF 20     // padded smem row stride (floats): conflict-free LDS.128
#define TILEF (1024*ROWF)   // 20480 floats = 80 KB per stage

// ---- scratch (no allocations allowed) ----
__device__ float g_pv[HC * B * D];       // 4 MB  partial v
__device__ float g_v[B * D];             // 128 KB v[b,d]
__device__ float g_pacc[B * NCHB * D];   // 512 KB per-CTA weighted partial sums
__device__ float g_pm[B * NCHB];
__device__ float g_pz[B * NCHB];
__device__ float g_ctx[B * D];           // final normalized context

__device__ __forceinline__ void cp_async16(uint32_t sa, const void* ga) {
    asm volatile("cp.async.cg.shared.global [%0], [%1], 16;" :: "r"(sa), "l"(ga));
}
__device__ __forceinline__ void mbar_init(uint32_t a, uint32_t cnt) {
    asm volatile("mbarrier.init.shared.b64 [%0], %1;" :: "r"(a), "r"(cnt) : "memory");
}
__device__ __forceinline__ void mbar_arrive(uint32_t a) {
    asm volatile("mbarrier.arrive.shared.b64 _, [%0];" :: "r"(a) : "memory");
}
// .noinc is load-bearing: barrier is pre-initialized with the arrival count,
// so the async-completion arrive must CONSUME a slot, not add-then-consume.
__device__ __forceinline__ void cpasync_mbar_arrive_noinc(uint32_t a) {
    asm volatile("cp.async.mbarrier.arrive.noinc.shared::cta.b64 [%0];" :: "r"(a) : "memory");
}
__device__ __forceinline__ void mbar_wait(uint32_t a, int parity) {
    asm volatile(
        "{\n\t.reg .pred P;\n\t"
        "W_%=:\n\t"
        "mbarrier.try_wait.parity.acquire.cta.shared::cta.b64 P, [%0], %1, 0x989680;\n\t"
        "@!P bra W_%=;\n\t}"
        :: "r"(a), "r"(parity) : "memory");
}

// ---------- Kernel A: partial v ----------
__global__ void vpart_kernel(const float* __restrict__ W, const float* __restrict__ hid) {
    __shared__ float sh[B][HCH];
    const int tid = threadIdx.x;                 // 128
    const int d   = blockIdx.x * 128 + tid;
    const int h0  = blockIdx.y * HCH;
    for (int i = tid; i < B * HCH; i += 128) {
        int b = i / HCH, h = i % HCH;
        sh[b][h] = hid[b * H + h0 + h];
    }
    __syncthreads();
    float acc[B];
#pragma unroll
    for (int b = 0; b < B; b++) acc[b] = 0.f;
#pragma unroll 8
    for (int h = 0; h < HCH; h++) {
        float w = W[(size_t)(h0 + h) * D + d];
#pragma unroll
        for (int b = 0; b < B; b++) acc[b] += w * sh[b][h];
    }
    float* outp = g_pv + (size_t)blockIdx.y * (B * D);
#pragma unroll
    for (int b = 0; b < B; b++) outp[b * D + d] = acc[b];
}

// ---------- Kernel B: reduce -> g_v ----------
__global__ void vreduce_kernel() {
    int i = blockIdx.x * 256 + threadIdx.x;
    const float4* src = reinterpret_cast<const float4*>(g_pv) + i;
    float4 s = make_float4(0.f, 0.f, 0.f, 0.f);
#pragma unroll 8
    for (int hc = 0; hc < HC; hc++) {
        float4 p = src[(size_t)hc * (B * D / 4)];
        s.x += p.x; s.y += p.y; s.z += p.z; s.w += p.w;
    }
    reinterpret_cast<float4*>(g_v)[i] = s;
}

// ---------- Kernel C: warp-specialized producer/consumer pipeline ----------
// smem: [0:32B) 4 mbarriers (full0,full1,empty0,empty1); tile[2] @ float 32; red[2][8*ROWF]
extern __shared__ float smem[];
__global__ void __launch_bounds__(512, 1) main_kernel(const float* __restrict__ ctx) {
    const int tid = threadIdx.x;
    const int b   = blockIdx.y;
    const int grp = blockIdx.x;            // 0..NCHB-1
    const uint32_t sbase = (uint32_t)__cvta_generic_to_shared(smem);
    float* tile = smem + 32;
    float* red  = smem + 32 + 2 * TILEF;   // 2 x 8*ROWF floats

    if (tid == 0) {
#pragma unroll
        for (int s = 0; s < 2; s++) {
            mbar_init(sbase + s * 8, 256);        // full[s]: 256 producer completions
            mbar_init(sbase + 16 + s * 8, 256);   // empty[s]: 256 consumer arrives
        }
    }
    __syncthreads();

    const float* cbase = ctx + (size_t)b * D * C + grp * (CCH * GCH);

    if (tid >= 256) {
        // ================= PRODUCER (warps 8-15) =================
        const int t    = tid - 256;
        const int colq = t & 3;            // 16B quarter of 64B row
        const int rowi = t >> 2;           // 0..63
        const float* srcb = cbase + colq * 4;
        int phase = 1;                     // first empty-wait passes immediately
        for (int g = 0; g < GCH; g++) {
            const int s = g & 1;
            mbar_wait(sbase + 16 + s * 8, phase);
            const float* src = srcb + g * CCH;
            const uint32_t dst = sbase + 128 + (uint32_t)s * (TILEF * 4) + colq * 16;
#pragma unroll
            for (int k = 0; k < 16; k++) {
                const int row = k * 64 + rowi;
                cp_async16(dst + row * (ROWF * 4), src + (size_t)row * C);
            }
            cpasync_mbar_arrive_noinc(sbase + s * 8);
            if (s == 1) phase ^= 1;
        }
    } else {
        // ================= CONSUMER (warps 0-7) =================
        const int lane = tid & 31;
        const int w    = tid >> 5;         // 0..7
        const int r    = lane & 7;
        const int cq   = lane >> 3;        // 0..3 (cols 4cq..4cq+3)
        const int drow = w * 8 + r;        // 0..63
        const int col  = lane & 15;
        const int half = lane >> 4;

        float vr[16];
#pragma unroll
        for (int i = 0; i < 16; i++)
            vr[i] = __ldg(&g_v[b * D + 64 * i + drow]);

        float accR[16];
#pragma unroll
        for (int i = 0; i < 16; i++) accR[i] = 0.f;
        float m_run = -1e30f, z_run = 0.f;
        int phase = 0;

        for (int g = 0; g < GCH; g++) {
            const int s = g & 1;
            mbar_wait(sbase + s * 8, phase);
            const float* tl = tile + s * TILEF + cq * 4;
            float* rbuf = red + (g & 1) * (8 * ROWF);

            // Phase 1: partial scores for own 4 columns over own 128 rows
            float p0 = 0.f, p1 = 0.f, p2 = 0.f, p3 = 0.f;
#pragma unroll
            for (int i = 0; i < 16; i++) {
                float4 x = *reinterpret_cast<const float4*>(tl + (64 * i + drow) * ROWF);
                p0 += x.x * vr[i];  p1 += x.y * vr[i];
                p2 += x.z * vr[i];  p3 += x.w * vr[i];
            }
#pragma unroll
            for (int o = 1; o <= 4; o <<= 1) {      // reduce over r (octet)
                p0 += __shfl_xor_sync(0xffffffffu, p0, o);
                p1 += __shfl_xor_sync(0xffffffffu, p1, o);
                p2 += __shfl_xor_sync(0xffffffffu, p2, o);
                p3 += __shfl_xor_sync(0xffffffffu, p3, o);
            }
            if (r == 0) {
                rbuf[w * ROWF + 4 * cq + 0] = p0;
                rbuf[w * ROWF + 4 * cq + 1] = p1;
                rbuf[w * ROWF + 4 * cq + 2] = p2;
                rbuf[w * ROWF + 4 * cq + 3] = p3;
            }
            asm volatile("bar.sync 1, 256;" ::: "memory");

            // Every consumer warp: column sums over 8 warps + softmax stats
            float part = 0.f;
#pragma unroll
            for (int j = 0; j < 4; j++)
                part += rbuf[(half * 4 + j) * ROWF + col];
            part += __shfl_xor_sync(0xffffffffu, part, 16);
            float m = part;
#pragma unroll
            for (int o = 1; o <= 8; o <<= 1) m = fmaxf(m, __shfl_xor_sync(0xffffffffu, m, o));
            float e = __expf(part - m);
            float z = e;
#pragma unroll
            for (int o = 1; o <= 8; o <<= 1) z += __shfl_xor_sync(0xffffffffu, z, o);

            const float w0 = __shfl_sync(0xffffffffu, e, 4 * cq + 0, 16);
            const float w1 = __shfl_sync(0xffffffffu, e, 4 * cq + 1, 16);
            const float w2 = __shfl_sync(0xffffffffu, e, 4 * cq + 2, 16);
            const float w3 = __shfl_sync(0xffffffffu, e, 4 * cq + 3, 16);

            // Phase 2: re-read tile, per-lane partial accumulate + flash rescale
            const float m_new = fmaxf(m_run, m);
            const float alpha = __expf(m_run - m_new);
            const float beta  = __expf(m - m_new);
#pragma unroll
            for (int i = 0; i < 16; i++) {
                float4 x = *reinterpret_cast<const float4*>(tl + (64 * i + drow) * ROWF);
                float t = x.x * w0 + x.y * w1 + x.z * w2 + x.w * w3;
                accR[i] = accR[i] * alpha + t * beta;
            }
            z_run = z_run * alpha + z * beta;
            m_run = m_new;

            mbar_arrive(sbase + 16 + s * 8);    // release stage
            if (s == 1) phase ^= 1;
        }

        // Epilogue: reduce deferred cq partials (lane bits 3,4)
#pragma unroll
        for (int i = 0; i < 16; i++) {
            accR[i] += __shfl_xor_sync(0xffffffffu, accR[i], 8);
            accR[i] += __shfl_xor_sync(0xffffffffu, accR[i], 16);
        }
        if (lane < 8) {
            float* dst = g_pacc + (size_t)(b * NCHB + grp) * D;
#pragma unroll
            for (int i = 0; i < 16; i++) dst[64 * i + w * 8 + lane] = accR[i];
        }
        if (tid == 0) { g_pm[b * NCHB + grp] = m_run; g_pz[b * NCHB + grp] = z_run; }
    }
}

// ---------- Kernel D1: combine 4 chunk partials -> g_ctx ----------
__global__ void combine_kernel() {
    __shared__ float pm[NCHB], pz[NCHB], fsh[NCHB];
    __shared__ float inv_sh;
    __shared__ float4 part[NCHB][64];
    const int b   = blockIdx.x;
    const int ds  = blockIdx.y;            // 0..3 d-slice (256 d's)
    const int tid = threadIdx.x;           // 256
    const int f4  = tid & 63;
    const int grp = tid >> 6;              // 0..3 = chunk entry

    if (tid < NCHB) { pm[tid] = g_pm[b * NCHB + tid]; pz[tid] = g_pz[b * NCHB + tid]; }
    __syncthreads();
    if (tid < NCHB) {
        float M = -1e30f;
#pragma unroll
        for (int ch = 0; ch < NCHB; ch++) M = fmaxf(M, pm[ch]);
        fsh[tid] = __expf(pm[tid] - M);
        if (tid == 0) {
            float Z = 0.f;
#pragma unroll
            for (int ch = 0; ch < NCHB; ch++) Z += pz[ch] * __expf(pm[ch] - M);
            inv_sh = 1.0f / Z;
        }
    }
    __syncthreads();

    float4 p = reinterpret_cast<const float4*>(
        g_pacc + (size_t)(b * NCHB + grp) * D + ds * 256)[f4];
    const float f = fsh[grp];
    part[grp][f4] = make_float4(p.x * f, p.y * f, p.z * f, p.w * f);
    __syncthreads();

    if (tid < 64) {
        float4 s = make_float4(0.f, 0.f, 0.f, 0.f);
#pragma unroll
        for (int g = 0; g < NCHB; g++) {
            float4 q = part[g][tid];
            s.x += q.x; s.y += q.y; s.z += q.z; s.w += q.w;
        }
        const float inv = inv_sh;
        s.x *= inv; s.y *= inv; s.z *= inv; s.w *= inv;
        reinterpret_cast<float4*>(g_ctx + b * D + ds * 256)[tid] = s;
    }
}

// ---------- Kernel D2: broadcast (write-bound, g_ctx L2-resident) ----------
__global__ void bcast_kernel(float4* __restrict__ out, int total4) {
    int i = blockIdx.x * 256 + threadIdx.x;
    if (i < total4)
        out[i] = reinterpret_cast<const float4*>(g_ctx)[i & (B * D / 4 - 1)];
}

extern "C" void kernel_launch(void* const* d_in, const int* in_sizes, int n_in,
                              void* d_out, int out_size) {
    // inputs: [0]=seqlen(int32), [1]=hidden f32 [1,B,H], [2]=contextvects f32 [B,D,C],
    //         [3]=W f32 [H,D], [4]=b f32 [H] (bias is softmax-invariant -> unused)
    const float* hid = (const float*)d_in[1];
    const float* ctx = (const float*)d_in[2];
    const float* W   = (const float*)d_in[3];

    vpart_kernel<<<dim3(8, HC), 128>>>(W, hid);
    vreduce_kernel<<<32, 256>>>();

    const size_t smemC = (size_t)(32 + 2 * TILEF + 2 * 8 * ROWF) * sizeof(float); // ~161.5 KB
    cudaFuncSetAttribute(main_kernel, cudaFuncAttributeMaxDynamicSharedMemorySize, (int)smemC);
    main_kernel<<<dim3(NCHB, B), 512, smemC>>>(ctx);

    combine_kernel<<<dim3(B, 4), 256>>>();

    const int total4 = out_size / 4;
    bcast_kernel<<<(total4 + 255) / 256, 256>>>((float4*)d_out, total4);
}